// round 12
// baseline (speedup 1.0000x reference)
#include <cuda_runtime.h>
#include <cuda_fp16.h>
#include <math.h>
#include <stdint.h>

#define S_LEN 128
#define BATCH 128
#define VOCAB 10000
#define NPAD  10240
#define EMB   512
#define HID   512

// ---------------- scratch (device globals: allocation-free) ----------------
__device__ float g_A0[S_LEN * BATCH * HID];   // emb proj (feeds G0 epilogue)
__device__ float g_Z1[S_LEN * BATCH * HID];   // h0[t]@W1x^T + b1 (feeds G1 epilogue)
__device__ float g_H0[S_LEN * BATCH * HID];   // only t=127 written
__device__ float g_H1[S_LEN * BATCH * HID];   // only t=127 written
// per-group, per-row-slab progress counters: [grp][slab] stride 32 u32 (128B)
__device__ unsigned g_barv[3 * 8 * 32];

// fp16 operands (embed + logits GEMMs)
__device__ __half g_embS [VOCAB * 1536];           // [hi|hi|lo]
__device__ __half g_W0xS [HID * 1536];             // [hi|lo|hi]
__device__ __half g_WoutH[NPAD * 512];
__device__ __half g_H1H  [S_LEN * BATCH * 512];

// recurrence operands, dedup [hi|lo], all stride 1024
__device__ __half g_W0hS[HID * 1024];
__device__ __half g_W1xS[HID * 1024];
__device__ __half g_W1hS[HID * 1024];
__device__ __half g_L0A [(S_LEN + 1) * BATCH * 1024];  // h0 split per t
__device__ __half g_L1A [(S_LEN + 1) * BATCH * 1024];  // h1 split per t

// =================== helpers ========================
__device__ __forceinline__ uint32_t smem_u32(const void* p) {
    uint32_t a;
    asm("{ .reg .u64 t; cvta.to.shared.u64 t, %1; cvt.u32.u64 %0, t; }" : "=r"(a) : "l"(p));
    return a;
}

#define CP_ASYNC16(dst, src) \
    asm volatile("cp.async.cg.shared.global [%0], [%1], 16;" :: "r"(dst), "l"(src) : "memory")
#define CP_COMMIT() asm volatile("cp.async.commit_group;" ::: "memory")
#define CP_WAIT1()  asm volatile("cp.async.wait_group 1;" ::: "memory")
#define CP_WAIT3()  asm volatile("cp.async.wait_group 3;" ::: "memory")

#define LDMATRIX_X4(r0, r1, r2, r3, addr) \
    asm volatile("ldmatrix.sync.aligned.m8n8.x4.shared.b16 {%0,%1,%2,%3}, [%4];" \
                 : "=r"(r0), "=r"(r1), "=r"(r2), "=r"(r3) : "r"(addr))

#define MMA16816(c, a0, a1, a2, a3, b0, b1) \
    asm volatile("mma.sync.aligned.m16n8k16.row.col.f32.f16.f16.f32 " \
        "{%0,%1,%2,%3},{%4,%5,%6,%7},{%8,%9},{%10,%11,%12,%13};" \
        : "=f"((c)[0]), "=f"((c)[1]), "=f"((c)[2]), "=f"((c)[3]) \
        : "r"(a0), "r"(a1), "r"(a2), "r"(a3), "r"(b0), "r"(b1), \
          "f"((c)[0]), "f"((c)[1]), "f"((c)[2]), "f"((c)[3]))

#define POLL_GE(ptr, target) do {                                          \
    unsigned _v;                                                           \
    do { asm volatile("ld.acquire.gpu.global.u32 %0, [%1];"                \
                      : "=r"(_v) : "l"(ptr)); } while (_v < (target));     \
} while (0)

#define RED_RELEASE(ptr) \
    asm volatile("red.release.gpu.global.add.u32 [%0], %1;" :: "l"(ptr), "r"(1u) : "memory")

// ======================= fused prep kernel ===========================
#define PREP_ROWS 22544

__global__ void prep_kernel(const float* __restrict__ emb,
                            const float* __restrict__ W0,
                            const float* __restrict__ W1,
                            const float* __restrict__ Wout,
                            const float* __restrict__ hidden)
{
    int i = blockIdx.x * blockDim.x + threadIdx.x;
    if (i >= PREP_ROWS * 512) return;
    int r = i >> 9, c = i & 511;

    if (r < 12048) {
        float x; __half* dst; long long ld; int mode, rr;
        if (r < 10000)      { rr = r;         x = emb[(size_t)rr * 512 + c];
                              dst = g_embS;  ld = 1536; mode = 0; }
        else if (r < 10512) { rr = r - 10000; x = W0[(size_t)rr * 1024 + c];
                              dst = g_W0xS;  ld = 1536; mode = 1; }
        else if (r < 11024) { rr = r - 10512; x = W0[(size_t)rr * 1024 + 512 + c];
                              dst = g_W0hS;  ld = 1024; mode = 2; }
        else if (r < 11536) { rr = r - 11024; x = W1[(size_t)rr * 1024 + c];
                              dst = g_W1xS;  ld = 1024; mode = 2; }
        else                { rr = r - 11536; x = W1[(size_t)rr * 1024 + 512 + c];
                              dst = g_W1hS;  ld = 1024; mode = 2; }
        __half hi = __float2half_rn(x);
        __half lo = __float2half_rn(x - __half2float(hi));
        size_t base = (size_t)rr * ld;
        dst[base + c] = hi;
        if (mode == 1)      { dst[base + 512 + c] = lo; dst[base + 1024 + c] = hi; }
        else if (mode == 0) { dst[base + 512 + c] = hi; dst[base + 1024 + c] = lo; }
        else                { dst[base + 512 + c] = lo; }
    } else if (r < 22288) {
        int rr = r - 12048;
        float x = (rr < VOCAB) ? Wout[(size_t)rr * 512 + c] : 0.0f;
        g_WoutH[(size_t)rr * 512 + c] = __float2half_rn(x);
    } else {
        int is_l1 = (r >= 22416);
        int rr = is_l1 ? (r - 22416) : (r - 22288);
        float x = hidden[(size_t)(is_l1 ? BATCH * HID : 0) + (size_t)rr * 512 + c];
        __half hi = __float2half_rn(x);
        __half lo = __float2half_rn(x - __half2float(hi));
        __half* dst = is_l1 ? g_L1A : g_L0A;
        size_t b = (size_t)rr * 1024;
        dst[b + c] = hi; dst[b + 512 + c] = lo;
    }
}

// ============= fp16 mma.sync GEMM (unchanged, proven) ===========
#define GEMM_SMEM (4 * 128 * 128)

__global__ void __launch_bounds__(256) gemm_fp16_mma(
    const __half* __restrict__ A,
    const int* __restrict__ gather,
    const __half* __restrict__ B,
    const float* __restrict__ bias,
    float* __restrict__ C, int ldc, int Nreal, int K)
{
    extern __shared__ __align__(1024) char smem[];
    const uint32_t sbase = smem_u32(smem);
    const uint32_t offA[2] = { 0u, 16384u };
    const uint32_t offB[2] = { 32768u, 49152u };

    const int tid  = threadIdx.x;
    const int lane = tid & 31;
    const int w    = tid >> 5;
    const int wm   = w >> 2;
    const int wn   = w & 3;
    const int m0   = blockIdx.y * 128;
    const int n0   = blockIdx.x * 128;

    const __half* asrc[4]; uint32_t adst[4];
    const __half* bsrc[4]; uint32_t bdst[4];
#pragma unroll
    for (int j = 0; j < 4; j++) {
        int id = tid + j * 256;
        int r = id >> 3, c = id & 7;
        int row = m0 + r;
        if (gather) row = gather[row];
        asrc[j] = A + (size_t)row * K + c * 8;
        adst[j] = (uint32_t)(r * 128 + ((c ^ (r & 7)) << 4));
        bsrc[j] = B + (size_t)(n0 + r) * K + c * 8;
        bdst[j] = adst[j];
    }

    float acc[4][4][4];
#pragma unroll
    for (int i = 0; i < 4; i++)
#pragma unroll
        for (int j = 0; j < 4; j++)
#pragma unroll
            for (int k = 0; k < 4; k++) acc[i][j][k] = 0.0f;

#pragma unroll
    for (int j = 0; j < 4; j++) {
        CP_ASYNC16(sbase + offA[0] + adst[j], asrc[j]);
        CP_ASYNC16(sbase + offB[0] + bdst[j], bsrc[j]);
    }
    CP_COMMIT();

    const int nst = K >> 6;
#pragma unroll 1
    for (int s = 0; s < nst; s++) {
        if (s + 1 < nst) {
            const int nb = (s + 1) & 1;
            const int ke = (s + 1) * 64;
#pragma unroll
            for (int j = 0; j < 4; j++) {
                CP_ASYNC16(sbase + offA[nb] + adst[j], asrc[j] + ke);
                CP_ASYNC16(sbase + offB[nb] + bdst[j], bsrc[j] + ke);
            }
        }
        CP_COMMIT();
        CP_WAIT1();
        __syncthreads();

        const uint32_t aBase = sbase + offA[s & 1];
        const uint32_t bBase = sbase + offB[s & 1];

#pragma unroll
        for (int kk = 0; kk < 4; kk++) {
            uint32_t aR[4][4], bR[4][2];
#pragma unroll
            for (int t = 0; t < 4; t++) {
                int row = wm * 64 + t * 16 + (lane & 15);
                int c   = kk * 2 + (lane >> 4);
                uint32_t ad = aBase + (uint32_t)(row * 128 + ((c ^ (row & 7)) << 4));
                LDMATRIX_X4(aR[t][0], aR[t][1], aR[t][2], aR[t][3], ad);
            }
#pragma unroll
            for (int p = 0; p < 2; p++) {
                int nrow = wn * 32 + p * 16 + (lane & 7) + ((lane >> 4) << 3);
                int c    = kk * 2 + ((lane >> 3) & 1);
                uint32_t bd = bBase + (uint32_t)(nrow * 128 + ((c ^ (nrow & 7)) << 4));
                uint32_t r0, r1, r2, r3;
                LDMATRIX_X4(r0, r1, r2, r3, bd);
                bR[p * 2 + 0][0] = r0; bR[p * 2 + 0][1] = r1;
                bR[p * 2 + 1][0] = r2; bR[p * 2 + 1][1] = r3;
            }
#pragma unroll
            for (int i = 0; i < 4; i++)
#pragma unroll
                for (int j = 0; j < 4; j++)
                    MMA16816(acc[i][j], aR[i][0], aR[i][1], aR[i][2], aR[i][3],
                             bR[j][0], bR[j][1]);
        }
        __syncthreads();
    }

    const int g  = lane >> 2;
    const int tg = lane & 3;
#pragma unroll
    for (int j = 0; j < 4; j++) {
        int col = n0 + wn * 32 + j * 8 + tg * 2;
        if (col >= Nreal) continue;
        float2 bv = *(const float2*)&bias[col];
#pragma unroll
        for (int i = 0; i < 4; i++) {
            int r0 = m0 + wm * 64 + i * 16 + g;
            float2 v0 = make_float2(acc[i][j][0] + bv.x, acc[i][j][1] + bv.y);
            float2 v1 = make_float2(acc[i][j][2] + bv.x, acc[i][j][3] + bv.y);
            *(float2*)&C[(size_t)r0 * ldc + col]       = v0;
            *(float2*)&C[(size_t)(r0 + 8) * ldc + col] = v1;
        }
    }
}

// ====== tensor-core recurrent kernel v6 (per-row-slab warp sync) ==========
// 96 CTAs, identical geometry: tile 128x16, K=1024 dedup [hi|lo].
//  G0 (bid  0..31): h0[t]  = tanh(A0[t] + h0[t-1] @ W0h^T)
//  GX (bid 32..63): z1x[t] = h0[t] @ W1x^T + b1
//  G1 (bid 64..95): h1[t]  = tanh(z1x[t] + h1[t-1] @ W1h^T)
// Sync: counter per (group, row-slab w). Warp w of each CTA arrives with
// red.release; consumer warp w polls with ld.acquire. NO block syncs in loop.
#define REC_CTAS 96
#define REC_AOFF 32768
#define REC_SMEM (32768 + 8 * 4 * 4096)   // 163840

__global__ void reset_barrier_kernel() {
    int i = threadIdx.x;
    if (i < 3 * 8 * 32) g_barv[i] = 0u;
}

__global__ void __launch_bounds__(256) rnn_rec_tc(const float* __restrict__ b1)
{
    extern __shared__ __align__(1024) char smem[];
    const uint32_t sbase = smem_u32(smem);
    const int bid  = blockIdx.x;
    const int tid  = threadIdx.x;
    const int lane = tid & 31;
    const int w    = tid >> 5;              // row slab 0..7
    const int grp  = bid >> 5;              // 0=G0, 1=GX, 2=G1
    const int nbase = (bid & 31) * 16;

    const __half* Wsrc = (grp == 0) ? g_W0hS : (grp == 1) ? g_W1xS : g_W1hS;
    const __half* Asrc = (grp == 2) ? g_L1A : g_L0A;

    // counters for this warp's row slab
    unsigned* cnt_own  = &g_barv[grp * 256 + w * 32];
    unsigned* cnt_dep0 = &g_barv[((grp == 0) ? 0 : (grp == 1) ? 0 : 1) * 256 + w * 32];
    unsigned* cnt_dep1 = &g_barv[2 * 256 + w * 32];    // G1's own-chain counter

    // ---- W slice resident: 16 blocks of [16 x 128B], swizzled (32KB) ----
    for (int id = tid; id < 2048; id += 256) {
        int u = id >> 7, rem = id & 127;
        int r = rem >> 3, c8 = rem & 7;
        uint32_t off = (uint32_t)(u * 2048 + r * 128 + ((c8 ^ (r & 7)) << 4));
        *(uint4*)(smem + off) =
            *(const uint4*)(Wsrc + (size_t)(nbase + r) * 1024 + u * 64 + c8 * 8);
    }
    __syncthreads();

    const uint32_t awbase = sbase + REC_AOFF + (uint32_t)w * 16384u;
    int arow8[8], acol8[8]; uint32_t adst8[8];
#pragma unroll
    for (int j = 0; j < 8; j++) {
        int id = lane + j * 32;
        int blk = id >> 7, rem = id & 127;
        int r = rem >> 3, c8 = rem & 7;
        arow8[j] = r;
        acol8[j] = blk * 64 + c8 * 8;
        adst8[j] = (uint32_t)(blk * 2048 + r * 128 + ((c8 ^ (r & 7)) << 4));
    }

#pragma unroll 1
    for (int t = 0; t < S_LEN; t++) {
        // ---- per-warp dependency wait (lane 0 polls, syncwarp broadcasts) ----
        if (lane == 0) {
            if (grp == 0) {
                if (t > 0) POLL_GE(cnt_dep0, 32u * (unsigned)t);         // h0[t-1]
            } else if (grp == 1) {
                POLL_GE(cnt_dep0, 32u * (unsigned)(t + 1));              // h0[t]
            } else {
                POLL_GE(cnt_dep0, 32u * (unsigned)(t + 1));              // z1x[t]
                if (t > 0) POLL_GE(cnt_dep1, 32u * (unsigned)t);         // h1[t-1]
            }
        }
        __syncwarp();

        // ---- warp-local compute (identical path for all groups) ----
        const int tA = (grp == 1) ? (t + 1) : t;   // GX reads h0[t] = L0A slot t+1
        const __half* Ab = Asrc + (size_t)tA * BATCH * 1024 + (size_t)(w * 16) * 1024;
        const __half* aptr8[8];
#pragma unroll
        for (int j = 0; j < 8; j++)
            aptr8[j] = Ab + (size_t)arow8[j] * 1024 + acol8[j];

        float acc[2][4];
#pragma unroll
        for (int i = 0; i < 2; i++)
#pragma unroll
            for (int k = 0; k < 4; k++) acc[i][k] = 0.0f;

#define RECW_ISSUE(ss, bi) do {                                            \
    uint32_t buf = awbase + (uint32_t)(bi) * 4096u;                        \
    CP_ASYNC16(buf + adst8[0], aptr8[0] + (ss) * 128);                     \
    CP_ASYNC16(buf + adst8[1], aptr8[1] + (ss) * 128);                     \
    CP_ASYNC16(buf + adst8[2], aptr8[2] + (ss) * 128);                     \
    CP_ASYNC16(buf + adst8[3], aptr8[3] + (ss) * 128);                     \
    CP_ASYNC16(buf + adst8[4], aptr8[4] + (ss) * 128);                     \
    CP_ASYNC16(buf + adst8[5], aptr8[5] + (ss) * 128);                     \
    CP_ASYNC16(buf + adst8[6], aptr8[6] + (ss) * 128);                     \
    CP_ASYNC16(buf + adst8[7], aptr8[7] + (ss) * 128);                     \
} while (0)

        RECW_ISSUE(0, 0); CP_COMMIT();
        RECW_ISSUE(1, 1); CP_COMMIT();
        RECW_ISSUE(2, 2); CP_COMMIT();

#pragma unroll 1
        for (int s = 0; s < 8; s++) {
            if (s + 3 < 8) { __syncwarp(); RECW_ISSUE(s + 3, (s + 3) & 3); }
            CP_COMMIT();
            CP_WAIT3();
            __syncwarp();

            const uint32_t aB = awbase + (uint32_t)(s & 3) * 4096u;

#pragma unroll
            for (int b = 0; b < 2; b++) {
                const int u = 2 * s + b;                // 0..15
                const bool hiseg = (u < 8);
                const int ut0 = hiseg ? u : (u - 8);

                uint32_t aR[4][4];
#pragma unroll
                for (int kk = 0; kk < 4; kk++) {
                    int arow = lane & 15;
                    int ac   = kk * 2 + (lane >> 4);
                    LDMATRIX_X4(aR[kk][0], aR[kk][1], aR[kk][2], aR[kk][3],
                                aB + (uint32_t)(b * 2048 + arow * 128 +
                                                ((ac ^ (arow & 7)) << 4)));
                }
                const int ntgt = hiseg ? 2 : 1;
#pragma unroll
                for (int tg_ = 0; tg_ < 2; tg_++) {
                    if (tg_ >= ntgt) break;
                    const int ut = (tg_ == 0) ? ut0 : (u + 8);
                    const uint32_t wB = sbase + (uint32_t)(ut * 2048);
#pragma unroll
                    for (int kk = 0; kk < 4; kk++) {
                        int brow = (lane & 7) + ((lane >> 4) << 3);
                        int bc   = kk * 2 + ((lane >> 3) & 1);
                        uint32_t b0, b1r, b2, b3;
                        LDMATRIX_X4(b0, b1r, b2, b3,
                                    wB + (uint32_t)(brow * 128 +
                                                    ((bc ^ (brow & 7)) << 4)));
                        MMA16816(acc[0], aR[kk][0], aR[kk][1], aR[kk][2], aR[kk][3], b0, b1r);
                        MMA16816(acc[1], aR[kk][0], aR[kk][1], aR[kk][2], aR[kk][3], b2, b3);
                    }
                }
            }
        }

        // ---- epilogue (per group) ----
        const int g = lane >> 2, tg = lane & 3;
        if (grp == 0) {
            const float* A0t = g_A0 + (size_t)t * BATCH * HID;
            __half* l0n = g_L0A + (size_t)(t + 1) * BATCH * 1024;
#pragma unroll
            for (int j = 0; j < 2; j++) {
                int col = nbase + j * 8 + tg * 2;
#pragma unroll
                for (int h = 0; h < 2; h++) {
                    int brow = w * 16 + g + h * 8;
                    float2 a0v = *(const float2*)&A0t[(size_t)brow * 512 + col];
                    float x0 = tanhf(acc[j][h * 2 + 0] + a0v.x);
                    float x1 = tanhf(acc[j][h * 2 + 1] + a0v.y);
                    __half h0 = __float2half_rn(x0), h1 = __float2half_rn(x1);
                    __half l0 = __float2half_rn(x0 - __half2float(h0));
                    __half l1 = __float2half_rn(x1 - __half2float(h1));
                    size_t r0 = (size_t)brow * 1024;
                    *(__half2*)&l0n[r0 + col]       = __halves2half2(h0, h1);
                    *(__half2*)&l0n[r0 + 512 + col] = __halves2half2(l0, l1);
                    if (t == S_LEN - 1)
                        *(float2*)&g_H0[((size_t)t * BATCH + brow) * 512 + col] =
                            make_float2(x0, x1);
                }
            }
        } else if (grp == 1) {
            float* Zt = g_Z1 + (size_t)t * BATCH * HID;
#pragma unroll
            for (int j = 0; j < 2; j++) {
                int col = nbase + j * 8 + tg * 2;
                float2 bv = *(const float2*)&b1[col];
#pragma unroll
                for (int h = 0; h < 2; h++) {
                    int brow = w * 16 + g + h * 8;
                    *(float2*)&Zt[(size_t)brow * 512 + col] =
                        make_float2(acc[j][h * 2 + 0] + bv.x, acc[j][h * 2 + 1] + bv.y);
                }
            }
        } else {
            const float* Zt = g_Z1 + (size_t)t * BATCH * HID;
            __half* l1n = g_L1A + (size_t)(t + 1) * BATCH * 1024;
#pragma unroll
            for (int j = 0; j < 2; j++) {
                int col = nbase + j * 8 + tg * 2;
#pragma unroll
                for (int h = 0; h < 2; h++) {
                    int brow = w * 16 + g + h * 8;
                    float2 zv = *(const float2*)&Zt[(size_t)brow * 512 + col];
                    float x0 = tanhf(acc[j][h * 2 + 0] + zv.x);
                    float x1 = tanhf(acc[j][h * 2 + 1] + zv.y);
                    __half h0 = __float2half_rn(x0), h1 = __float2half_rn(x1);
                    __half l0 = __float2half_rn(x0 - __half2float(h0));
                    __half l1 = __float2half_rn(x1 - __half2float(h1));
                    size_t r1 = (size_t)brow * 1024;
                    *(__half2*)&l1n[r1 + col]       = __halves2half2(h0, h1);
                    *(__half2*)&l1n[r1 + 512 + col] = __halves2half2(l0, l1);
                    *(__half2*)&g_H1H[((size_t)t * BATCH + brow) * 512 + col] =
                        __halves2half2(h0, h1);
                    if (t == S_LEN - 1)
                        *(float2*)&g_H1[((size_t)t * BATCH + brow) * 512 + col] =
                            make_float2(x0, x1);
                }
            }
        }

        // ---- per-warp release-arrive on own slab counter ----
        __syncwarp();
        if (lane == 0) {
            __threadfence();
            RED_RELEASE(cnt_own);
        }
    }
}

// ---------------------------------------------------------------------------
__global__ void copy_hidden_kernel(float* __restrict__ dst)
{
    const int BH = BATCH * HID;
    int i = blockIdx.x * blockDim.x + threadIdx.x;
    if (i < BH)           dst[i] = g_H0[(size_t)(S_LEN - 1) * BH + i];
    else if (i < 2 * BH)  dst[i] = g_H1[(size_t)(S_LEN - 1) * BH + (i - BH)];
}

// ---------------------------------------------------------------------------
extern "C" void kernel_launch(void* const* d_in, const int* in_sizes, int n_in,
                              void* d_out, int out_size)
{
    const int*   inputs = (const int*)  d_in[0];
    const float* hidden = (const float*)d_in[1];
    const float* emb    = (const float*)d_in[2];
    const float* W0     = (const float*)d_in[3];
    const float* b0     = (const float*)d_in[4];
    const float* W1     = (const float*)d_in[5];
    const float* b1     = (const float*)d_in[6];
    const float* Wout   = (const float*)d_in[7];
    const float* bout   = (const float*)d_in[8];
    float* out = (float*)d_out;

    cudaFuncSetAttribute(gemm_fp16_mma, cudaFuncAttributeMaxDynamicSharedMemorySize,
                         GEMM_SMEM);
    cudaFuncSetAttribute(rnn_rec_tc, cudaFuncAttributeMaxDynamicSharedMemorySize,
                         REC_SMEM);

    __half *embS, *w0xS, *woutH, *h1H;
    float *a0;
    cudaGetSymbolAddress((void**)&embS,  g_embS);
    cudaGetSymbolAddress((void**)&w0xS,  g_W0xS);
    cudaGetSymbolAddress((void**)&woutH, g_WoutH);
    cudaGetSymbolAddress((void**)&h1H,   g_H1H);
    cudaGetSymbolAddress((void**)&a0,    g_A0);

    // 1) counters reset
    reset_barrier_kernel<<<1, 768>>>();

    // 2) fused operand prep
    prep_kernel<<<(PREP_ROWS * 512 + 255) / 256, 256>>>(emb, W0, W1, Wout, hidden);

    // 3) input projection (HMMA, 3-term K=1536): g_A0 = emb[tok] @ W0x^T + b0
    {
        dim3 grid(HID / 128, (S_LEN * BATCH) / 128);
        gemm_fp16_mma<<<grid, 256, GEMM_SMEM>>>(embS, inputs, w0xS, b0, a0, HID, HID, 1536);
    }

    // 4) recurrence: per-row-slab warp-synced pipeline
    rnn_rec_tc<<<REC_CTAS, 256, REC_SMEM>>>(b1);

    // 5) logits = H1 @ Wout^T + bout (HMMA, K=512)
    {
        dim3 grid(NPAD / 128, (S_LEN * BATCH) / 128);
        gemm_fp16_mma<<<grid, 256, GEMM_SMEM>>>(h1H, nullptr, woutH, bout, out, VOCAB,
                                                VOCAB, 512);
    }

    // 6) final hidden tail if the output buffer carries it
    long long need = (long long)S_LEN * BATCH * VOCAB + 2LL * BATCH * HID;
    if ((long long)out_size >= need) {
        float* tail = out + (size_t)S_LEN * BATCH * VOCAB;
        copy_hidden_kernel<<<(2 * BATCH * HID) / 256, 256>>>(tail);
    }
}

// round 14
// speedup vs baseline: 1.1822x; 1.1822x over previous
#include <cuda_runtime.h>
#include <cuda_fp16.h>
#include <math.h>
#include <stdint.h>

#define S_LEN 128
#define BATCH 128
#define VOCAB 10000
#define NPAD  10240
#define EMB   512
#define HID   512
#define NTILES (S_LEN * (NPAD / 128))   // 128 * 80 = 10240 logits tiles

// ---------------- scratch (device globals: allocation-free) ----------------
__device__ float g_A0[S_LEN * BATCH * HID];   // emb proj (feeds G0 epilogue)
__device__ float g_Z1[S_LEN * BATCH * HID];   // h0[t]@W1x^T + b1 (feeds G1 epilogue)
__device__ float g_H0[S_LEN * BATCH * HID];   // only t=127 written
__device__ float g_H1[S_LEN * BATCH * HID];   // only t=127 written
__device__ unsigned g_bar0;     // G0 (h0 chain) progress
__device__ unsigned g_barX;     // GX (z1x) progress
__device__ unsigned g_bar1;     // G1 (h1 chain) progress
__device__ unsigned g_tileq;    // logits tile work queue

// fp16 operands (embed + logits GEMMs)
__device__ __half g_embS [VOCAB * 1536];           // [hi|hi|lo]
__device__ __half g_W0xS [HID * 1536];             // [hi|lo|hi]
__device__ __half g_WoutH[NPAD * 512];
__device__ __half g_H1H  [S_LEN * BATCH * 512];

// recurrence operands, dedup [hi|lo], all stride 1024
__device__ __half g_W0hS[HID * 1024];
__device__ __half g_W1xS[HID * 1024];
__device__ __half g_W1hS[HID * 1024];
__device__ __half g_L0A [(S_LEN + 1) * BATCH * 1024];  // h0 split per t
__device__ __half g_L1A [(S_LEN + 1) * BATCH * 1024];  // h1 split per t

// =================== helpers ========================
__device__ __forceinline__ uint32_t smem_u32(const void* p) {
    uint32_t a;
    asm("{ .reg .u64 t; cvta.to.shared.u64 t, %1; cvt.u32.u64 %0, t; }" : "=r"(a) : "l"(p));
    return a;
}

#define CP_ASYNC16(dst, src) \
    asm volatile("cp.async.cg.shared.global [%0], [%1], 16;" :: "r"(dst), "l"(src) : "memory")
#define CP_COMMIT() asm volatile("cp.async.commit_group;" ::: "memory")
#define CP_WAIT1()  asm volatile("cp.async.wait_group 1;" ::: "memory")
#define CP_WAIT3()  asm volatile("cp.async.wait_group 3;" ::: "memory")

#define LDMATRIX_X4(r0, r1, r2, r3, addr) \
    asm volatile("ldmatrix.sync.aligned.m8n8.x4.shared.b16 {%0,%1,%2,%3}, [%4];" \
                 : "=r"(r0), "=r"(r1), "=r"(r2), "=r"(r3) : "r"(addr))

#define MMA16816(c, a0, a1, a2, a3, b0, b1) \
    asm volatile("mma.sync.aligned.m16n8k16.row.col.f32.f16.f16.f32 " \
        "{%0,%1,%2,%3},{%4,%5,%6,%7},{%8,%9},{%10,%11,%12,%13};" \
        : "=f"((c)[0]), "=f"((c)[1]), "=f"((c)[2]), "=f"((c)[3]) \
        : "r"(a0), "r"(a1), "r"(a2), "r"(a3), "r"(b0), "r"(b1), \
          "f"((c)[0]), "f"((c)[1]), "f"((c)[2]), "f"((c)[3]))

#define POLL_GE(ptr, target) do {                                          \
    unsigned _v;                                                           \
    do { asm volatile("ld.acquire.gpu.global.u32 %0, [%1];"                \
                      : "=r"(_v) : "l"(ptr)); } while (_v < (target));     \
} while (0)

// ======================= fused prep kernel ===========================
#define PREP_ROWS 22544

__global__ void prep_kernel(const float* __restrict__ emb,
                            const float* __restrict__ W0,
                            const float* __restrict__ W1,
                            const float* __restrict__ Wout,
                            const float* __restrict__ hidden)
{
    int i = blockIdx.x * blockDim.x + threadIdx.x;
    if (i >= PREP_ROWS * 512) return;
    int r = i >> 9, c = i & 511;

    if (r < 12048) {
        float x; __half* dst; long long ld; int mode, rr;
        if (r < 10000)      { rr = r;         x = emb[(size_t)rr * 512 + c];
                              dst = g_embS;  ld = 1536; mode = 0; }
        else if (r < 10512) { rr = r - 10000; x = W0[(size_t)rr * 1024 + c];
                              dst = g_W0xS;  ld = 1536; mode = 1; }
        else if (r < 11024) { rr = r - 10512; x = W0[(size_t)rr * 1024 + 512 + c];
                              dst = g_W0hS;  ld = 1024; mode = 2; }
        else if (r < 11536) { rr = r - 11024; x = W1[(size_t)rr * 1024 + c];
                              dst = g_W1xS;  ld = 1024; mode = 2; }
        else                { rr = r - 11536; x = W1[(size_t)rr * 1024 + 512 + c];
                              dst = g_W1hS;  ld = 1024; mode = 2; }
        __half hi = __float2half_rn(x);
        __half lo = __float2half_rn(x - __half2float(hi));
        size_t base = (size_t)rr * ld;
        dst[base + c] = hi;
        if (mode == 1)      { dst[base + 512 + c] = lo; dst[base + 1024 + c] = hi; }
        else if (mode == 0) { dst[base + 512 + c] = hi; dst[base + 1024 + c] = lo; }
        else                { dst[base + 512 + c] = lo; }
    } else if (r < 22288) {
        int rr = r - 12048;
        float x = (rr < VOCAB) ? Wout[(size_t)rr * 512 + c] : 0.0f;
        g_WoutH[(size_t)rr * 512 + c] = __float2half_rn(x);
    } else {
        int is_l1 = (r >= 22416);
        int rr = is_l1 ? (r - 22416) : (r - 22288);
        float x = hidden[(size_t)(is_l1 ? BATCH * HID : 0) + (size_t)rr * 512 + c];
        __half hi = __float2half_rn(x);
        __half lo = __float2half_rn(x - __half2float(hi));
        __half* dst = is_l1 ? g_L1A : g_L0A;
        size_t b = (size_t)rr * 1024;
        dst[b + c] = hi; dst[b + 512 + c] = lo;
    }
}

// ============= 128x128 fp16 tile GEMM body (shared device fn) ===========
__device__ __forceinline__ void tile_gemm128(
    char* smem, uint32_t sbase,
    const __half* __restrict__ A, const int* __restrict__ gather,
    const __half* __restrict__ B, const float* __restrict__ bias,
    float* __restrict__ C, int ldc, int Nreal, int K, int m0, int n0)
{
    const uint32_t offA[2] = { 0u, 16384u };
    const uint32_t offB[2] = { 32768u, 49152u };
    const int tid  = threadIdx.x;
    const int lane = tid & 31;
    const int w    = tid >> 5;
    const int wm   = w >> 2;
    const int wn   = w & 3;

    const __half* asrc[4]; uint32_t adst[4];
    const __half* bsrc[4]; uint32_t bdst[4];
#pragma unroll
    for (int j = 0; j < 4; j++) {
        int id = tid + j * 256;
        int r = id >> 3, c = id & 7;
        int row = m0 + r;
        if (gather) row = gather[row];
        asrc[j] = A + (size_t)row * K + c * 8;
        adst[j] = (uint32_t)(r * 128 + ((c ^ (r & 7)) << 4));
        bsrc[j] = B + (size_t)(n0 + r) * K + c * 8;
        bdst[j] = adst[j];
    }

    float acc[4][4][4];
#pragma unroll
    for (int i = 0; i < 4; i++)
#pragma unroll
        for (int j = 0; j < 4; j++)
#pragma unroll
            for (int k = 0; k < 4; k++) acc[i][j][k] = 0.0f;

#pragma unroll
    for (int j = 0; j < 4; j++) {
        CP_ASYNC16(sbase + offA[0] + adst[j], asrc[j]);
        CP_ASYNC16(sbase + offB[0] + bdst[j], bsrc[j]);
    }
    CP_COMMIT();

    const int nst = K >> 6;
#pragma unroll 1
    for (int s = 0; s < nst; s++) {
        if (s + 1 < nst) {
            const int nb = (s + 1) & 1;
            const int ke = (s + 1) * 64;
#pragma unroll
            for (int j = 0; j < 4; j++) {
                CP_ASYNC16(sbase + offA[nb] + adst[j], asrc[j] + ke);
                CP_ASYNC16(sbase + offB[nb] + bdst[j], bsrc[j] + ke);
            }
        }
        CP_COMMIT();
        CP_WAIT1();
        __syncthreads();

        const uint32_t aBase = sbase + offA[s & 1];
        const uint32_t bBase = sbase + offB[s & 1];

#pragma unroll
        for (int kk = 0; kk < 4; kk++) {
            uint32_t aR[4][4], bR[4][2];
#pragma unroll
            for (int t = 0; t < 4; t++) {
                int row = wm * 64 + t * 16 + (lane & 15);
                int c   = kk * 2 + (lane >> 4);
                uint32_t ad = aBase + (uint32_t)(row * 128 + ((c ^ (row & 7)) << 4));
                LDMATRIX_X4(aR[t][0], aR[t][1], aR[t][2], aR[t][3], ad);
            }
#pragma unroll
            for (int p = 0; p < 2; p++) {
                int nrow = wn * 32 + p * 16 + (lane & 7) + ((lane >> 4) << 3);
                int c    = kk * 2 + ((lane >> 3) & 1);
                uint32_t bd = bBase + (uint32_t)(nrow * 128 + ((c ^ (nrow & 7)) << 4));
                uint32_t r0, r1, r2, r3;
                LDMATRIX_X4(r0, r1, r2, r3, bd);
                bR[p * 2 + 0][0] = r0; bR[p * 2 + 0][1] = r1;
                bR[p * 2 + 1][0] = r2; bR[p * 2 + 1][1] = r3;
            }
#pragma unroll
            for (int i = 0; i < 4; i++)
#pragma unroll
                for (int j = 0; j < 4; j++)
                    MMA16816(acc[i][j], aR[i][0], aR[i][1], aR[i][2], aR[i][3],
                             bR[j][0], bR[j][1]);
        }
        __syncthreads();
    }

    const int g  = lane >> 2;
    const int tg = lane & 3;
#pragma unroll
    for (int j = 0; j < 4; j++) {
        int col = n0 + wn * 32 + j * 8 + tg * 2;
        if (col >= Nreal) continue;
        float2 bv = *(const float2*)&bias[col];
#pragma unroll
        for (int i = 0; i < 4; i++) {
            int r0 = m0 + wm * 64 + i * 16 + g;
            float2 v0 = make_float2(acc[i][j][0] + bv.x, acc[i][j][1] + bv.y);
            float2 v1 = make_float2(acc[i][j][2] + bv.x, acc[i][j][3] + bv.y);
            *(float2*)&C[(size_t)r0 * ldc + col]       = v0;
            *(float2*)&C[(size_t)(r0 + 8) * ldc + col] = v1;
        }
    }
}

// standalone GEMM (embed projection)
#define GEMM_SMEM (4 * 128 * 128)
__global__ void __launch_bounds__(256) gemm_fp16_mma(
    const __half* __restrict__ A, const int* __restrict__ gather,
    const __half* __restrict__ B, const float* __restrict__ bias,
    float* __restrict__ C, int ldc, int Nreal, int K)
{
    extern __shared__ __align__(1024) char smem[];
    tile_gemm128(smem, smem_u32(smem), A, gather, B, bias, C, ldc, Nreal, K,
                 blockIdx.y * 128, blockIdx.x * 128);
}

// ====== fused persistent kernel: recurrence (96 CTAs) + logits stealing =====
#define FUSED_CTAS 148
#define REC_AOFF 32768
#define SLOT_TILE (32768 + 8 * 4 * 4096)         // 163840: dedicated tail slot
#define REC_SMEM (32768 + 8 * 4 * 4096 + 1024)   // 164864

__global__ void reset_barrier_kernel() {
    g_bar0 = 0u; g_barX = 0u; g_bar1 = 0u; g_tileq = 0u;
}

__global__ void __launch_bounds__(256) fused_rec_logits(
    const float* __restrict__ b1, const float* __restrict__ bout,
    float* __restrict__ out)
{
    extern __shared__ __align__(1024) char smem[];
    const uint32_t sbase = smem_u32(smem);
    const int bid  = blockIdx.x;
    const int tid  = threadIdx.x;
    const int lane = tid & 31;
    const int w    = tid >> 5;

    if (bid < 96) {
        // =================== recurrence (R11-proven path) ===================
        const int grp  = bid >> 5;              // 0=G0, 1=GX, 2=G1
        const int nbase = (bid & 31) * 16;
        const __half* Wsrc = (grp == 0) ? g_W0hS : (grp == 1) ? g_W1xS : g_W1hS;
        const __half* Asrc = (grp == 2) ? g_L1A : g_L0A;

        for (int id = tid; id < 2048; id += 256) {
            int u = id >> 7, rem = id & 127;
            int r = rem >> 3, c8 = rem & 7;
            uint32_t off = (uint32_t)(u * 2048 + r * 128 + ((c8 ^ (r & 7)) << 4));
            *(uint4*)(smem + off) =
                *(const uint4*)(Wsrc + (size_t)(nbase + r) * 1024 + u * 64 + c8 * 8);
        }
        __syncthreads();

        const uint32_t awbase = sbase + REC_AOFF + (uint32_t)w * 16384u;
        int arow8[8], acol8[8]; uint32_t adst8[8];
#pragma unroll
        for (int j = 0; j < 8; j++) {
            int id = lane + j * 32;
            int blk = id >> 7, rem = id & 127;
            int r = rem >> 3, c8 = rem & 7;
            arow8[j] = r;
            acol8[j] = blk * 64 + c8 * 8;
            adst8[j] = (uint32_t)(blk * 2048 + r * 128 + ((c8 ^ (r & 7)) << 4));
        }

#pragma unroll 1
        for (int t = 0; t < S_LEN; t++) {
            if (tid == 0) {
                if (grp == 0) {
                    if (t > 0) POLL_GE(&g_bar0, 32u * (unsigned)t);
                } else if (grp == 1) {
                    POLL_GE(&g_bar0, 32u * (unsigned)(t + 1));
                } else {
                    POLL_GE(&g_barX, 32u * (unsigned)(t + 1));
                    if (t > 0) POLL_GE(&g_bar1, 32u * (unsigned)t);
                }
            }
            __syncthreads();

            const int tA = (grp == 1) ? (t + 1) : t;
            const __half* Ab = Asrc + (size_t)tA * BATCH * 1024 + (size_t)(w * 16) * 1024;
            const __half* aptr8[8];
#pragma unroll
            for (int j = 0; j < 8; j++)
                aptr8[j] = Ab + (size_t)arow8[j] * 1024 + acol8[j];

            float acc[2][4];
#pragma unroll
            for (int i = 0; i < 2; i++)
#pragma unroll
                for (int k = 0; k < 4; k++) acc[i][k] = 0.0f;

#define RECW_ISSUE(ss, bi) do {                                            \
    uint32_t buf = awbase + (uint32_t)(bi) * 4096u;                        \
    CP_ASYNC16(buf + adst8[0], aptr8[0] + (ss) * 128);                     \
    CP_ASYNC16(buf + adst8[1], aptr8[1] + (ss) * 128);                     \
    CP_ASYNC16(buf + adst8[2], aptr8[2] + (ss) * 128);                     \
    CP_ASYNC16(buf + adst8[3], aptr8[3] + (ss) * 128);                     \
    CP_ASYNC16(buf + adst8[4], aptr8[4] + (ss) * 128);                     \
    CP_ASYNC16(buf + adst8[5], aptr8[5] + (ss) * 128);                     \
    CP_ASYNC16(buf + adst8[6], aptr8[6] + (ss) * 128);                     \
    CP_ASYNC16(buf + adst8[7], aptr8[7] + (ss) * 128);                     \
} while (0)

            RECW_ISSUE(0, 0); CP_COMMIT();
            RECW_ISSUE(1, 1); CP_COMMIT();
            RECW_ISSUE(2, 2); CP_COMMIT();

#pragma unroll 1
            for (int s = 0; s < 8; s++) {
                if (s + 3 < 8) { __syncwarp(); RECW_ISSUE(s + 3, (s + 3) & 3); }
                CP_COMMIT();
                CP_WAIT3();
                __syncwarp();

                const uint32_t aB = awbase + (uint32_t)(s & 3) * 4096u;

#pragma unroll
                for (int b = 0; b < 2; b++) {
                    const int u = 2 * s + b;
                    const bool hiseg = (u < 8);
                    const int ut0 = hiseg ? u : (u - 8);

                    uint32_t aR[4][4];
#pragma unroll
                    for (int kk = 0; kk < 4; kk++) {
                        int arow = lane & 15;
                        int ac   = kk * 2 + (lane >> 4);
                        LDMATRIX_X4(aR[kk][0], aR[kk][1], aR[kk][2], aR[kk][3],
                                    aB + (uint32_t)(b * 2048 + arow * 128 +
                                                    ((ac ^ (arow & 7)) << 4)));
                    }
                    const int ntgt = hiseg ? 2 : 1;
#pragma unroll
                    for (int tg_ = 0; tg_ < 2; tg_++) {
                        if (tg_ >= ntgt) break;
                        const int ut = (tg_ == 0) ? ut0 : (u + 8);
                        const uint32_t wB = sbase + (uint32_t)(ut * 2048);
#pragma unroll
                        for (int kk = 0; kk < 4; kk++) {
                            int brow = (lane & 7) + ((lane >> 4) << 3);
                            int bc   = kk * 2 + ((lane >> 3) & 1);
                            uint32_t b0, b1r, b2, b3;
                            LDMATRIX_X4(b0, b1r, b2, b3,
                                        wB + (uint32_t)(brow * 128 +
                                                        ((bc ^ (brow & 7)) << 4)));
                            MMA16816(acc[0], aR[kk][0], aR[kk][1], aR[kk][2], aR[kk][3], b0, b1r);
                            MMA16816(acc[1], aR[kk][0], aR[kk][1], aR[kk][2], aR[kk][3], b2, b3);
                        }
                    }
                }
            }

            const int g = lane >> 2, tg = lane & 3;
            if (grp == 0) {
                const float* A0t = g_A0 + (size_t)t * BATCH * HID;
                __half* l0n = g_L0A + (size_t)(t + 1) * BATCH * 1024;
#pragma unroll
                for (int j = 0; j < 2; j++) {
                    int col = nbase + j * 8 + tg * 2;
#pragma unroll
                    for (int h = 0; h < 2; h++) {
                        int brow = w * 16 + g + h * 8;
                        float2 a0v = *(const float2*)&A0t[(size_t)brow * 512 + col];
                        float x0 = tanhf(acc[j][h * 2 + 0] + a0v.x);
                        float x1 = tanhf(acc[j][h * 2 + 1] + a0v.y);
                        __half h0 = __float2half_rn(x0), h1 = __float2half_rn(x1);
                        __half l0 = __float2half_rn(x0 - __half2float(h0));
                        __half l1 = __float2half_rn(x1 - __half2float(h1));
                        size_t r0 = (size_t)brow * 1024;
                        *(__half2*)&l0n[r0 + col]       = __halves2half2(h0, h1);
                        *(__half2*)&l0n[r0 + 512 + col] = __halves2half2(l0, l1);
                        if (t == S_LEN - 1)
                            *(float2*)&g_H0[((size_t)t * BATCH + brow) * 512 + col] =
                                make_float2(x0, x1);
                    }
                }
            } else if (grp == 1) {
                float* Zt = g_Z1 + (size_t)t * BATCH * HID;
#pragma unroll
                for (int j = 0; j < 2; j++) {
                    int col = nbase + j * 8 + tg * 2;
                    float2 bv = *(const float2*)&b1[col];
#pragma unroll
                    for (int h = 0; h < 2; h++) {
                        int brow = w * 16 + g + h * 8;
                        *(float2*)&Zt[(size_t)brow * 512 + col] =
                            make_float2(acc[j][h * 2 + 0] + bv.x, acc[j][h * 2 + 1] + bv.y);
                    }
                }
            } else {
                const float* Zt = g_Z1 + (size_t)t * BATCH * HID;
                __half* l1n = g_L1A + (size_t)(t + 1) * BATCH * 1024;
#pragma unroll
                for (int j = 0; j < 2; j++) {
                    int col = nbase + j * 8 + tg * 2;
#pragma unroll
                    for (int h = 0; h < 2; h++) {
                        int brow = w * 16 + g + h * 8;
                        float2 zv = *(const float2*)&Zt[(size_t)brow * 512 + col];
                        float x0 = tanhf(acc[j][h * 2 + 0] + zv.x);
                        float x1 = tanhf(acc[j][h * 2 + 1] + zv.y);
                        __half h0 = __float2half_rn(x0), h1 = __float2half_rn(x1);
                        __half l0 = __float2half_rn(x0 - __half2float(h0));
                        __half l1 = __float2half_rn(x1 - __half2float(h1));
                        size_t r1 = (size_t)brow * 1024;
                        *(__half2*)&l1n[r1 + col]       = __halves2half2(h0, h1);
                        *(__half2*)&l1n[r1 + 512 + col] = __halves2half2(l0, l1);
                        *(__half2*)&g_H1H[((size_t)t * BATCH + brow) * 512 + col] =
                            __halves2half2(h0, h1);
                        if (t == S_LEN - 1)
                            *(float2*)&g_H1[((size_t)t * BATCH + brow) * 512 + col] =
                                make_float2(x0, x1);
                    }
                }
            }

            __syncthreads();
            __threadfence();
            if (tid == 0)
                atomicAdd((grp == 0) ? &g_bar0 : (grp == 1) ? &g_barX : &g_bar1, 1u);
        }
        __syncthreads();   // rec done; smem (incl. W slice + A ring) now dead
    }

    // ============== logits work-stealing loop (ALL CTAs) ==============
    volatile unsigned* slot = (volatile unsigned*)(smem + SLOT_TILE);
#pragma unroll 1
    for (;;) {
        if (tid == 0) *slot = atomicAdd(&g_tileq, 1u);
        __syncthreads();
        unsigned tile = *slot;
        __syncthreads();
        if (tile >= (unsigned)NTILES) break;
        int t  = (int)(tile / (NPAD / 128));
        int nt = (int)(tile % (NPAD / 128));
        if (tid == 0) POLL_GE(&g_bar1, 32u * (unsigned)(t + 1));   // h1[t] final
        __syncthreads();
        tile_gemm128(smem, sbase, g_H1H, nullptr, g_WoutH, bout,
                     out, VOCAB, VOCAB, 512, t * 128, nt * 128);
    }
}

// ---------------------------------------------------------------------------
__global__ void copy_hidden_kernel(float* __restrict__ dst)
{
    const int BH = BATCH * HID;
    int i = blockIdx.x * blockDim.x + threadIdx.x;
    if (i < BH)           dst[i] = g_H0[(size_t)(S_LEN - 1) * BH + i];
    else if (i < 2 * BH)  dst[i] = g_H1[(size_t)(S_LEN - 1) * BH + (i - BH)];
}

// ---------------------------------------------------------------------------
extern "C" void kernel_launch(void* const* d_in, const int* in_sizes, int n_in,
                              void* d_out, int out_size)
{
    const int*   inputs = (const int*)  d_in[0];
    const float* hidden = (const float*)d_in[1];
    const float* emb    = (const float*)d_in[2];
    const float* W0     = (const float*)d_in[3];
    const float* b0     = (const float*)d_in[4];
    const float* W1     = (const float*)d_in[5];
    const float* b1     = (const float*)d_in[6];
    const float* Wout   = (const float*)d_in[7];
    const float* bout   = (const float*)d_in[8];
    float* out = (float*)d_out;

    cudaFuncSetAttribute(gemm_fp16_mma, cudaFuncAttributeMaxDynamicSharedMemorySize,
                         GEMM_SMEM);
    cudaFuncSetAttribute(fused_rec_logits, cudaFuncAttributeMaxDynamicSharedMemorySize,
                         REC_SMEM);

    __half *embS, *w0xS;
    float *a0;
    cudaGetSymbolAddress((void**)&embS, g_embS);
    cudaGetSymbolAddress((void**)&w0xS, g_W0xS);
    cudaGetSymbolAddress((void**)&a0,   g_A0);

    // 1) counters reset
    reset_barrier_kernel<<<1, 1>>>();

    // 2) fused operand prep
    prep_kernel<<<(PREP_ROWS * 512 + 255) / 256, 256>>>(emb, W0, W1, Wout, hidden);

    // 3) input projection (HMMA, 3-term K=1536): g_A0 = emb[tok] @ W0x^T + b0
    {
        dim3 grid(HID / 128, (S_LEN * BATCH) / 128);
        gemm_fp16_mma<<<grid, 256, GEMM_SMEM>>>(embS, inputs, w0xS, b0, a0, HID, HID, 1536);
    }

    // 4) fused recurrence + overlapped logits GEMM (148 persistent CTAs)
    fused_rec_logits<<<FUSED_CTAS, 256, REC_SMEM>>>(b1, bout, out);

    // 5) final hidden tail if the output buffer carries it
    long long need = (long long)S_LEN * BATCH * VOCAB + 2LL * BATCH * HID;
    if ((long long)out_size >= need) {
        float* tail = out + (size_t)S_LEN * BATCH * VOCAB;
        copy_hidden_kernel<<<(2 * BATCH * HID) / 256, 256>>>(tail);
    }
}